// round 9
// baseline (speedup 1.0000x reference)
#include <cuda_runtime.h>
#include <cuda_bf16.h>

// Problem constants
#define B_   4
#define L_   256
#define DK   48      // D*K
#define D_   8
#define K_   6
#define A_   64
#define O_   64
#define DA   512     // D*A
#define BL   (B_ * L_)

typedef unsigned long long u64;

// Scratch (device globals). Tables hold e-factors: E = ex2(-logit*log2e) so
// exp(-logit_total) = E1[i] * E3[j-i] * C2 (multiplicative split of the sum).
__device__ float g_E1t[DK * BL];    // [dk][b*256+i]   transposed
__device__ float g_C2 [BL * DK];    // [b*256+j][dk]   row-major
__device__ float g_E3t[DK * L_];    // [dk][delta]     transposed
__device__ float g_S  [BL * DA];

#define NEG_LOG2E (-1.4426950408889634f)

__device__ __forceinline__ float ex2f(float x) {
    float r; asm("ex2.approx.f32 %0, %1;" : "=f"(r) : "f"(x)); return r;
}
__device__ __forceinline__ float rcpf(float x) {
    float r; asm("rcp.approx.f32 %0, %1;" : "=f"(r) : "f"(x)); return r;
}
__device__ __forceinline__ u64 pk2(float lo, float hi) {
    u64 r; asm("mov.b64 %0, {%1, %2};" : "=l"(r) : "f"(lo), "f"(hi)); return r;
}
__device__ __forceinline__ void unpk2(float& lo, float& hi, u64 v) {
    asm("mov.b64 {%0, %1}, %2;" : "=f"(lo), "=f"(hi) : "l"(v));
}
__device__ __forceinline__ u64 mul2(u64 a, u64 b) {
    u64 r; asm("mul.rn.f32x2 %0, %1, %2;" : "=l"(r) : "l"(a), "l"(b)); return r;
}
__device__ __forceinline__ u64 fma2(u64 a, u64 b, u64 c) {
    u64 r; asm("fma.rn.f32x2 %0, %1, %2, %3;" : "=l"(r) : "l"(a), "l"(b), "l"(c)); return r;
}

// ---------------------------------------------------------------------------
// Kernel A: partial e-factors. 144 blocks x 256 threads, 16 rows/block.
//   blocks 0-63: E1t, 64-127: C2 (row-major), 128-143: E3t.
//   Stores ex2(min(-logit*log2e, 30)).
// ---------------------------------------------------------------------------
__global__ void __launch_bounds__(256)
precompute_kernel(const float* __restrict__ in1,
                  const float* __restrict__ in2,
                  const float* __restrict__ pos,
                  const float* __restrict__ anchors) {
    __shared__ float sa[DK * 65];
    __shared__ float sx[16 * 65];

    const int t  = threadIdx.x;
    const int bi = blockIdx.x;

    int fo, row0, mode;   // mode 0: E1t, 1: C2 row-major, 2: E3t
    const float* src;
    if (bi < 64)       { fo = 0;   row0 = bi * 16;         src = in1; mode = 0; }
    else if (bi < 128) { fo = 64;  row0 = (bi - 64) * 16;  src = in2; mode = 1; }
    else               { fo = 128; row0 = (bi - 128) * 16; src = pos; mode = 2; }

    #pragma unroll
    for (int it = 0; it < 3; it++) {
        const int idx = t + it * 256;
        const int c   = idx >> 4;
        const int f4  = (idx & 15) << 2;
        const float4 v = *(const float4*)(anchors + c * 192 + fo + f4);
        float* d = &sa[c * 65 + f4];
        d[0] = v.x; d[1] = v.y; d[2] = v.z; d[3] = v.w;
    }
    {
        const int r   = t >> 4;
        const int f4  = (t & 15) << 2;
        const float4 v = *(const float4*)(src + (row0 + r) * 64 + f4);
        float* d = &sx[r * 65 + f4];
        d[0] = v.x; d[1] = v.y; d[2] = v.z; d[3] = v.w;
    }
    __syncthreads();

    const int rg = t & 15;    // row within slab
    const int cg = t >> 4;    // cols cg*3 .. cg*3+2

    float acc0 = 0.f, acc1 = 0.f, acc2 = 0.f;
    const float* a0 = &sa[(cg * 3 + 0) * 65];
    const float* a1 = &sa[(cg * 3 + 1) * 65];
    const float* a2 = &sa[(cg * 3 + 2) * 65];
    const float* x0 = &sx[rg * 65];

    #pragma unroll 16
    for (int f = 0; f < 64; f++) {
        const float xv = x0[f];
        acc0 = fmaf(xv, a0[f], acc0);
        acc1 = fmaf(xv, a1[f], acc1);
        acc2 = fmaf(xv, a2[f], acc2);
    }
    acc0 = ex2f(fminf(acc0 * NEG_LOG2E, 30.f));
    acc1 = ex2f(fminf(acc1 * NEG_LOG2E, 30.f));
    acc2 = ex2f(fminf(acc2 * NEG_LOG2E, 30.f));

    const int row = row0 + rg;
    const int col = cg * 3;
    if (mode == 0) {
        g_E1t[(col + 0) * BL + row] = acc0;
        g_E1t[(col + 1) * BL + row] = acc1;
        g_E1t[(col + 2) * BL + row] = acc2;
    } else if (mode == 1) {
        float* dp = &g_C2[row * DK + col];
        dp[0] = acc0; dp[1] = acc1; dp[2] = acc2;
    } else {
        g_E3t[(col + 0) * L_ + row] = acc0;
        g_E3t[(col + 1) * L_ + row] = acc1;
        g_E3t[(col + 2) * L_ + row] = acc2;
    }
}

// ---------------------------------------------------------------------------
// Kernel B: warp-autonomous pair loop. 1024 blocks x 256 threads, 128 regs.
//   warp-task = (b, j, d); lane owns i = pass*32 + lane.
//   Software-pipelined: pass p+1's 12 LDGs issued before pass p's compute.
//   e_k = E1*E3*C2 (no MUFU in loop except one rcp); f32x2 outer product.
// ---------------------------------------------------------------------------
__global__ void __launch_bounds__(256, 2)
pair_kernel() {
    __shared__ float red[8][32][33];   // per-warp transpose-reduce scratch

    const int wid  = threadIdx.x >> 5;
    const int lane = threadIdx.x & 31;
    const int task = blockIdx.x * 8 + wid;

    const int j   = (L_ - 1) - (task >> 5);   // big-j tasks first
    const int sub = task & 31;
    const int b   = sub & 3;
    const int d   = sub >> 2;
    const int dk0 = d * K_;

    const float* c2p = &g_C2[(b * L_ + j) * DK + dk0];
    const float c2_0 = c2p[0], c2_1 = c2p[1], c2_2 = c2p[2];
    const float c2_3 = c2p[3], c2_4 = c2p[4], c2_5 = c2p[5];

    u64 acc[8][4];   // [hi][lo-pair]
    #pragma unroll
    for (int h = 0; h < 8; h++)
        #pragma unroll
        for (int l = 0; l < 4; l++) acc[h][l] = 0ull;

    const float* e1b = &g_E1t[dk0 * BL + b * L_];
    const float* e3b = &g_E3t[dk0 * L_];
    const int npass = (j + 31) >> 5;

    // prefetch pass 0 (12 loads into registers)
    float na[6], nb[6];
    {
        const int i   = lane;
        const int icl = min(i, L_ - 1);
        const int o   = max(j - i, 0);
        #pragma unroll
        for (int k = 0; k < 6; k++) {
            na[k] = e1b[k * BL + icl];
            nb[k] = e3b[k * L_ + o];
        }
    }

    for (int p = 0; p < npass; p++) {
        const int i = p * 32 + lane;

        // consume prefetched values
        float ca[6], cb[6];
        #pragma unroll
        for (int k = 0; k < 6; k++) { ca[k] = na[k]; cb[k] = nb[k]; }

        // issue next pass's loads (clamped; masked lanes read harmless data)
        {
            const int i2  = (p + 1) * 32 + lane;
            const int icl = min(i2, L_ - 1);
            const int o2  = max(j - i2, 0);
            #pragma unroll
            for (int k = 0; k < 6; k++) {
                na[k] = e1b[k * BL + icl];
                nb[k] = e3b[k * L_ + o2];
            }
        }

        // e_k = E1*E3*C2, clamped to 2^20 (fminf also scrubs NaN from junk lanes)
        const float e0 = fminf(ca[0] * (cb[0] * c2_0), 1048576.f);
        const float e1 = fminf(ca[1] * (cb[1] * c2_1), 1048576.f);
        const float e2 = fminf(ca[2] * (cb[2] * c2_2), 1048576.f);
        const float e3 = fminf(ca[3] * (cb[3] * c2_3), 1048576.f);
        const float e4 = fminf(ca[4] * (cb[4] * c2_4), 1048576.f);
        const float e5 = fminf(ca[5] * (cb[5] * c2_5), 1048576.f);

        // Z = prod(1+e_k); one reciprocal, validity mask folded in
        const float z01 = (1.f + e0) * (1.f + e1);
        const float z23 = (1.f + e2) * (1.f + e3);
        const float z45 = (1.f + e4) * (1.f + e5);
        const float Z   = z01 * z23 * z45;
        const float m   = (i < j) ? 1.0f : 0.0f;
        const float rm  = rcpf(Z) * m;

        // lo tree (bits 0..2 on e0,e1,e2; bit=1 contributes 1):
        //   lo = {e0e1e2, e1e2, e0e2, e2, e0e1, e1, e0, 1}
        const float c01 = e0 * e1;
        const u64 P01 = pk2(c01, e1);
        const u64 P23 = pk2(e0, 1.f);
        const u64 E2b = pk2(e2, e2);
        u64 LO[4];
        LO[0] = mul2(P01, E2b);
        LO[1] = mul2(P23, E2b);
        LO[2] = P01;
        LO[3] = P23;

        // hi tree (bits 3..5 on e3,e4,e5), scaled by rm
        const float c34  = e3 * e4;
        const float e5rm = e5 * rm;
        float hi[8];
        hi[0] = c34 * e5rm;
        hi[1] = e4 * e5rm;
        hi[2] = e3 * e5rm;
        hi[3] = e5rm;
        hi[4] = c34 * rm;
        hi[5] = e4 * rm;
        hi[6] = e3 * rm;
        hi[7] = rm;

        // 8x8 outer product, f32x2 packed (32 FFMA2)
        #pragma unroll
        for (int h = 0; h < 8; h++) {
            const u64 hb = pk2(hi[h], hi[h]);
            acc[h][0] = fma2(hb, LO[0], acc[h][0]);
            acc[h][1] = fma2(hb, LO[1], acc[h][1]);
            acc[h][2] = fma2(hb, LO[2], acc[h][2]);
            acc[h][3] = fma2(hb, LO[3], acc[h][3]);
        }
    }

    // unpack to scalar [h][l]
    float av[8][8];
    #pragma unroll
    for (int h = 0; h < 8; h++)
        #pragma unroll
        for (int l = 0; l < 4; l++)
            unpk2(av[h][2 * l], av[h][2 * l + 1], acc[h][l]);

    // warp transpose-reduce: 64 values x 32 lanes -> S[d][64]
    float (*rw)[33] = red[wid];
    const int col  = lane & 15;
    const int half = lane >> 4;
    float* sbase = &g_S[((size_t)(b * L_ + j)) * DA + d * A_];

    #pragma unroll
    for (int c = 0; c < 4; c++) {
        #pragma unroll
        for (int m2 = 0; m2 < 8; m2++) {
            rw[lane][m2]     = av[2 * c][m2];
            rw[lane][8 + m2] = av[2 * c + 1][m2];
        }
        __syncwarp();
        float sum = 0.f;
        #pragma unroll
        for (int r = 0; r < 16; r++) sum += rw[half * 16 + r][col];
        sum += __shfl_xor_sync(0xffffffffu, sum, 16);
        if (lane < 16) sbase[c * 16 + col] = sum;
        __syncwarp();
    }
}

// ---------------------------------------------------------------------------
// Kernel C: out[row, o] = sum_da S[row, da] * W[da, o].
// 128 blocks (8 rows each) x 256 threads, split-k=2, 2x2 register tiles.
// ---------------------------------------------------------------------------
__global__ void __launch_bounds__(256)
final_gemm(const float* __restrict__ W, float* __restrict__ out) {
    __shared__ float sW[128 * 64];
    __shared__ float sS[8][132];
    __shared__ float red[128][4];

    const int t    = threadIdx.x;
    const int row0 = blockIdx.x * 8;
    const int kh   = t >> 7;
    const int u    = t & 127;
    const int tr   = u >> 5;
    const int tc   = u & 31;

    float a00 = 0.f, a01 = 0.f, a10 = 0.f, a11 = 0.f;

    for (int chnk = 0; chnk < 4; chnk++) {
        const int k0 = chnk * 128;
        const float4* Wv = (const float4*)(W + k0 * 64);
        #pragma unroll
        for (int it = 0; it < 8; it++)
            ((float4*)sW)[t + it * 256] = Wv[t + it * 256];
        {
            const int r  = t >> 5;
            const int c4 = (t & 31) << 2;
            const float4 v = *(const float4*)(&g_S[(row0 + r) * DA + k0 + c4]);
            float* dp = &sS[r][c4];
            dp[0] = v.x; dp[1] = v.y; dp[2] = v.z; dp[3] = v.w;
        }
        __syncthreads();

        const int kb = kh * 64;
        #pragma unroll 8
        for (int kk = 0; kk < 64; kk++) {
            const int k = kb + kk;
            const float2 w = *(const float2*)(&sW[k * 64 + tc * 2]);
            const float s0 = sS[tr * 2][k];
            const float s1 = sS[tr * 2 + 1][k];
            a00 = fmaf(s0, w.x, a00);
            a01 = fmaf(s0, w.y, a01);
            a10 = fmaf(s1, w.x, a10);
            a11 = fmaf(s1, w.y, a11);
        }
        __syncthreads();
    }

    if (kh == 1) {
        red[u][0] = a00; red[u][1] = a01; red[u][2] = a10; red[u][3] = a11;
    }
    __syncthreads();
    if (kh == 0) {
        a00 += red[u][0]; a01 += red[u][1]; a10 += red[u][2]; a11 += red[u][3];
        const int r = row0 + tr * 2, c = tc * 2;
        out[r * O_ + c]           = a00;
        out[r * O_ + c + 1]       = a01;
        out[(r + 1) * O_ + c]     = a10;
        out[(r + 1) * O_ + c + 1] = a11;
    }
}

// ---------------------------------------------------------------------------
extern "C" void kernel_launch(void* const* d_in, const int* in_sizes, int n_in,
                              void* d_out, int out_size) {
    const float* in1     = (const float*)d_in[0];
    const float* in2     = (const float*)d_in[1];
    const float* pos     = (const float*)d_in[2];
    const float* anchors = (const float*)d_in[3];
    const float* lut     = (const float*)d_in[4];
    float* out = (float*)d_out;

    precompute_kernel<<<144, 256>>>(in1, in2, pos, anchors);
    pair_kernel<<<1024, 256>>>();
    final_gemm<<<(B_ * L_) / 8, 256>>>(lut, out);
}

// round 10
// speedup vs baseline: 1.1892x; 1.1892x over previous
#include <cuda_runtime.h>
#include <cuda_bf16.h>

// Problem constants
#define B_   4
#define L_   256
#define DK   48      // D*K
#define D_   8
#define K_   6
#define A_   64
#define O_   64
#define DA   512     // D*A
#define BL   (B_ * L_)

typedef unsigned long long u64;

// Scratch (device globals). Tables hold e-factors: E = ex2(-logit*log2e) so
// exp(-logit_total) = E1[i] * E3[j-i] * C2 (multiplicative split of the sum).
__device__ float g_E1t[DK * BL];    // [dk][b*256+i]   transposed
__device__ float g_C2 [BL * DK];    // [b*256+j][dk]   row-major
__device__ float g_E3t[DK * L_];    // [dk][delta]     transposed
__device__ float g_S  [BL * DA];

#define NEG_LOG2E (-1.4426950408889634f)

__device__ __forceinline__ float ex2f(float x) {
    float r; asm("ex2.approx.f32 %0, %1;" : "=f"(r) : "f"(x)); return r;
}
__device__ __forceinline__ float rcpf(float x) {
    float r; asm("rcp.approx.f32 %0, %1;" : "=f"(r) : "f"(x)); return r;
}
__device__ __forceinline__ u64 pk2(float lo, float hi) {
    u64 r; asm("mov.b64 %0, {%1, %2};" : "=l"(r) : "f"(lo), "f"(hi)); return r;
}
__device__ __forceinline__ void unpk2(float& lo, float& hi, u64 v) {
    asm("mov.b64 {%0, %1}, %2;" : "=f"(lo), "=f"(hi) : "l"(v));
}
__device__ __forceinline__ u64 mul2(u64 a, u64 b) {
    u64 r; asm("mul.rn.f32x2 %0, %1, %2;" : "=l"(r) : "l"(a), "l"(b)); return r;
}
__device__ __forceinline__ u64 fma2(u64 a, u64 b, u64 c) {
    u64 r; asm("fma.rn.f32x2 %0, %1, %2, %3;" : "=l"(r) : "l"(a), "l"(b), "l"(c)); return r;
}

// ---------------------------------------------------------------------------
// Kernel A: partial e-factors. 144 blocks x 256 threads, 16 rows/block.
// ---------------------------------------------------------------------------
__global__ void __launch_bounds__(256)
precompute_kernel(const float* __restrict__ in1,
                  const float* __restrict__ in2,
                  const float* __restrict__ pos,
                  const float* __restrict__ anchors) {
    __shared__ float sa[DK * 65];
    __shared__ float sx[16 * 65];

    const int t  = threadIdx.x;
    const int bi = blockIdx.x;

    int fo, row0, mode;   // mode 0: E1t, 1: C2 row-major, 2: E3t
    const float* src;
    if (bi < 64)       { fo = 0;   row0 = bi * 16;         src = in1; mode = 0; }
    else if (bi < 128) { fo = 64;  row0 = (bi - 64) * 16;  src = in2; mode = 1; }
    else               { fo = 128; row0 = (bi - 128) * 16; src = pos; mode = 2; }

    #pragma unroll
    for (int it = 0; it < 3; it++) {
        const int idx = t + it * 256;
        const int c   = idx >> 4;
        const int f4  = (idx & 15) << 2;
        const float4 v = *(const float4*)(anchors + c * 192 + fo + f4);
        float* d = &sa[c * 65 + f4];
        d[0] = v.x; d[1] = v.y; d[2] = v.z; d[3] = v.w;
    }
    {
        const int r   = t >> 4;
        const int f4  = (t & 15) << 2;
        const float4 v = *(const float4*)(src + (row0 + r) * 64 + f4);
        float* d = &sx[r * 65 + f4];
        d[0] = v.x; d[1] = v.y; d[2] = v.z; d[3] = v.w;
    }
    __syncthreads();

    const int rg = t & 15;    // row within slab
    const int cg = t >> 4;    // cols cg*3 .. cg*3+2

    float acc0 = 0.f, acc1 = 0.f, acc2 = 0.f;
    const float* a0 = &sa[(cg * 3 + 0) * 65];
    const float* a1 = &sa[(cg * 3 + 1) * 65];
    const float* a2 = &sa[(cg * 3 + 2) * 65];
    const float* x0 = &sx[rg * 65];

    #pragma unroll 16
    for (int f = 0; f < 64; f++) {
        const float xv = x0[f];
        acc0 = fmaf(xv, a0[f], acc0);
        acc1 = fmaf(xv, a1[f], acc1);
        acc2 = fmaf(xv, a2[f], acc2);
    }
    acc0 = ex2f(fminf(acc0 * NEG_LOG2E, 30.f));
    acc1 = ex2f(fminf(acc1 * NEG_LOG2E, 30.f));
    acc2 = ex2f(fminf(acc2 * NEG_LOG2E, 30.f));

    const int row = row0 + rg;
    const int col = cg * 3;
    if (mode == 0) {
        g_E1t[(col + 0) * BL + row] = acc0;
        g_E1t[(col + 1) * BL + row] = acc1;
        g_E1t[(col + 2) * BL + row] = acc2;
    } else if (mode == 1) {
        float* dp = &g_C2[row * DK + col];
        dp[0] = acc0; dp[1] = acc1; dp[2] = acc2;
    } else {
        g_E3t[(col + 0) * L_ + row] = acc0;
        g_E3t[(col + 1) * L_ + row] = acc1;
        g_E3t[(col + 2) * L_ + row] = acc2;
    }
}

// ---------------------------------------------------------------------------
// Kernel B: warp-autonomous pair loop. 2048 blocks x 128 threads, 6 blocks/SM.
//   warp-task = (b, j, d); lane produces e/trees for its own i = p*32+lane.
//   Lane-pair split accumulation: even lanes accumulate addresses lo[0..3],
//   odd lanes lo[4..7], covering both lanes' i via one shfl_xor(1) exchange.
//   acc = 16 u64 (32 regs) -> fits 85-reg cap -> 6 warps/SMSP.
// ---------------------------------------------------------------------------
__global__ void __launch_bounds__(128, 6)
pair_kernel() {
    __shared__ float red[4][32][33];   // per-warp transpose-reduce scratch

    const int wid  = threadIdx.x >> 5;
    const int lane = threadIdx.x & 31;
    const int par  = lane & 1;
    const int task = blockIdx.x * 4 + wid;

    const int j   = (L_ - 1) - (task >> 5);   // big-j tasks first
    const int sub = task & 31;
    const int b   = sub & 3;
    const int d   = sub >> 2;
    const int dk0 = d * K_;

    const float* c2p = &g_C2[(b * L_ + j) * DK + dk0];
    const float c2_0 = c2p[0], c2_1 = c2p[1], c2_2 = c2p[2];
    const float c2_3 = c2p[3], c2_4 = c2p[4], c2_5 = c2p[5];

    u64 acc[8][2];   // [hi][own-half lo-pair]
    #pragma unroll
    for (int h = 0; h < 8; h++) { acc[h][0] = 0ull; acc[h][1] = 0ull; }

    const float* e1b = &g_E1t[dk0 * BL + b * L_];
    const float* e3b = &g_E3t[dk0 * L_];
    const int npass = (j + 31) >> 5;

    for (int p = 0; p < npass; p++) {
        const int i   = p * 32 + lane;
        const int icl = min(i, L_ - 1);
        const int o3  = max(j - i, 0);

        // e_k = E1*E3*C2, clamped to 2^20 (also scrubs junk-lane values)
        const float e0 = fminf(e1b[0 * BL + icl] * (e3b[0 * L_ + o3] * c2_0), 1048576.f);
        const float e1 = fminf(e1b[1 * BL + icl] * (e3b[1 * L_ + o3] * c2_1), 1048576.f);
        const float e2 = fminf(e1b[2 * BL + icl] * (e3b[2 * L_ + o3] * c2_2), 1048576.f);
        const float e3 = fminf(e1b[3 * BL + icl] * (e3b[3 * L_ + o3] * c2_3), 1048576.f);
        const float e4 = fminf(e1b[4 * BL + icl] * (e3b[4 * L_ + o3] * c2_4), 1048576.f);
        const float e5 = fminf(e1b[5 * BL + icl] * (e3b[5 * L_ + o3] * c2_5), 1048576.f);

        // Z = prod(1+e_k); one reciprocal, validity mask folded in
        const float Z  = ((1.f + e0) * (1.f + e1)) * ((1.f + e2) * (1.f + e3))
                       * ((1.f + e4) * (1.f + e5));
        const float m  = (i < j) ? 1.0f : 0.0f;
        const float rm = rcpf(Z) * m;

        // lo pairs: half-A = {e0e1e2, e1e2 | e0e2, e2}, half-B = {e0e1, e1 | e0, 1}
        const float c01 = e0 * e1;
        const u64 P01 = pk2(c01, e1);
        const u64 P23 = pk2(e0, 1.f);
        const u64 E2b = pk2(e2, e2);
        const u64 LA0 = mul2(P01, E2b);
        const u64 LA1 = mul2(P23, E2b);

        // exchange: send the half my partner accumulates
        const u64 s0 = par ? LA0 : P01;   // odd sends half-A, even sends half-B
        const u64 s1 = par ? LA1 : P23;
        const u64 rLO0 = __shfl_xor_sync(0xffffffffu, s0, 1);
        const u64 rLO1 = __shfl_xor_sync(0xffffffffu, s1, 1);
        const u64 kLO0 = par ? P01 : LA0; // keep my own half
        const u64 kLO1 = par ? P23 : LA1;

        // exchange hi ingredients, rebuild partner's hi
        const float re3 = __shfl_xor_sync(0xffffffffu, e3, 1);
        const float re4 = __shfl_xor_sync(0xffffffffu, e4, 1);
        const float re5 = __shfl_xor_sync(0xffffffffu, e5, 1);
        const float rrm = __shfl_xor_sync(0xffffffffu, rm, 1);

        const float c34  = e3 * e4,  e5rm = e5 * rm;
        const float rc34 = re3 * re4, re5rm = re5 * rrm;
        float hiO[8], hiP[8];
        hiO[0] = c34 * e5rm;  hiO[1] = e4 * e5rm;  hiO[2] = e3 * e5rm;  hiO[3] = e5rm;
        hiO[4] = c34 * rm;    hiO[5] = e4 * rm;    hiO[6] = e3 * rm;    hiO[7] = rm;
        hiP[0] = rc34 * re5rm; hiP[1] = re4 * re5rm; hiP[2] = re3 * re5rm; hiP[3] = re5rm;
        hiP[4] = rc34 * rrm;   hiP[5] = re4 * rrm;   hiP[6] = re3 * rrm;   hiP[7] = rrm;

        // 8x4 outer product x 2 sources (32 FFMA2)
        #pragma unroll
        for (int h = 0; h < 8; h++) {
            const u64 hbO = pk2(hiO[h], hiO[h]);
            const u64 hbP = pk2(hiP[h], hiP[h]);
            acc[h][0] = fma2(hbO, kLO0, acc[h][0]);
            acc[h][1] = fma2(hbO, kLO1, acc[h][1]);
            acc[h][0] = fma2(hbP, rLO0, acc[h][0]);
            acc[h][1] = fma2(hbP, rLO1, acc[h][1]);
        }
    }

    // unpack: av[h][t], t=0..3 -> address a = h*8 + par*4 + t
    float av[8][4];
    #pragma unroll
    for (int h = 0; h < 8; h++) {
        unpk2(av[h][0], av[h][1], acc[h][0]);
        unpk2(av[h][2], av[h][3], acc[h][1]);
    }

    // single-round transpose-reduce: red[lane][h*4+t]
    float (*rw)[33] = red[wid];
    #pragma unroll
    for (int h = 0; h < 8; h++) {
        #pragma unroll
        for (int t2 = 0; t2 < 4; t2++) rw[lane][h * 4 + t2] = av[h][t2];
    }
    __syncwarp();

    float* sbase = &g_S[((size_t)(b * L_ + j)) * DA + d * A_];
    #pragma unroll
    for (int half = 0; half < 2; half++) {
        const int o  = lane + half * 32;       // output address 0..63
        const int hh = o >> 3;
        const int l  = o & 7;
        const int pr = (l >> 2) & 1;           // parity of source lanes
        const int c  = hh * 4 + (l & 3);
        float sum = 0.f;
        #pragma unroll
        for (int k = 0; k < 16; k++) sum += rw[2 * k + pr][c];
        sbase[o] = sum;
    }
}

// ---------------------------------------------------------------------------
// Kernel C: out[row, o] = sum_da S[row, da] * W[da, o].
// 128 blocks (8 rows each) x 256 threads, split-k=2, 2x2 register tiles.
// ---------------------------------------------------------------------------
__global__ void __launch_bounds__(256)
final_gemm(const float* __restrict__ W, float* __restrict__ out) {
    __shared__ float sW[128 * 64];
    __shared__ float sS[8][132];
    __shared__ float red[128][4];

    const int t    = threadIdx.x;
    const int row0 = blockIdx.x * 8;
    const int kh   = t >> 7;
    const int u    = t & 127;
    const int tr   = u >> 5;
    const int tc   = u & 31;

    float a00 = 0.f, a01 = 0.f, a10 = 0.f, a11 = 0.f;

    for (int chnk = 0; chnk < 4; chnk++) {
        const int k0 = chnk * 128;
        const float4* Wv = (const float4*)(W + k0 * 64);
        #pragma unroll
        for (int it = 0; it < 8; it++)
            ((float4*)sW)[t + it * 256] = Wv[t + it * 256];
        {
            const int r  = t >> 5;
            const int c4 = (t & 31) << 2;
            const float4 v = *(const float4*)(&g_S[(row0 + r) * DA + k0 + c4]);
            float* dp = &sS[r][c4];
            dp[0] = v.x; dp[1] = v.y; dp[2] = v.z; dp[3] = v.w;
        }
        __syncthreads();

        const int kb = kh * 64;
        #pragma unroll 8
        for (int kk = 0; kk < 64; kk++) {
            const int k = kb + kk;
            const float2 w = *(const float2*)(&sW[k * 64 + tc * 2]);
            const float s0 = sS[tr * 2][k];
            const float s1 = sS[tr * 2 + 1][k];
            a00 = fmaf(s0, w.x, a00);
            a01 = fmaf(s0, w.y, a01);
            a10 = fmaf(s1, w.x, a10);
            a11 = fmaf(s1, w.y, a11);
        }
        __syncthreads();
    }

    if (kh == 1) {
        red[u][0] = a00; red[u][1] = a01; red[u][2] = a10; red[u][3] = a11;
    }
    __syncthreads();
    if (kh == 0) {
        a00 += red[u][0]; a01 += red[u][1]; a10 += red[u][2]; a11 += red[u][3];
        const int r = row0 + tr * 2, c = tc * 2;
        out[r * O_ + c]           = a00;
        out[r * O_ + c + 1]       = a01;
        out[(r + 1) * O_ + c]     = a10;
        out[(r + 1) * O_ + c + 1] = a11;
    }
}

// ---------------------------------------------------------------------------
extern "C" void kernel_launch(void* const* d_in, const int* in_sizes, int n_in,
                              void* d_out, int out_size) {
    const float* in1     = (const float*)d_in[0];
    const float* in2     = (const float*)d_in[1];
    const float* pos     = (const float*)d_in[2];
    const float* anchors = (const float*)d_in[3];
    const float* lut     = (const float*)d_in[4];
    float* out = (float*)d_out;

    precompute_kernel<<<144, 256>>>(in1, in2, pos, anchors);
    pair_kernel<<<2048, 128>>>();
    final_gemm<<<(B_ * L_) / 8, 256>>>(lut, out);
}